// round 3
// baseline (speedup 1.0000x reference)
#include <cuda_runtime.h>

#define B_ 8
#define L_ 1024
#define T_ 10
#define TILE 32
#define NT (L_/TILE)

// log(9.0)
#define S_CONST 2.1972245773362196f

// Scratch (allocation-free rule: __device__ globals)
__device__ float g_uu[(size_t)B_*L_*L_];
__device__ float g_ah[(size_t)B_*L_*L_];
__device__ float g_rowsum[B_*L_];
__device__ float g_lmbd[B_*L_];
__device__ float g_g[B_*L_];

__device__ __forceinline__ float sigm(float x){ return 1.0f/(1.0f+__expf(-x)); }
// soft_sign(x) = sigm(2x)  (K=1)

// m[i,j] from x rows: (ba,bu,bc,bg) = (x0,x1,x2,x3)
__device__ __forceinline__ float m_of(const float* xi, const float* xj){
    return xi[0]*xj[1] + xj[0]*xi[1]
         + xi[2]*xj[3] + xj[2]*xi[3]
         + xi[1]*xj[3] + xj[1]*xi[3];
}

// 3 -> 3(relu) -> 1(relu) MLP; W1 row-major (o,i), W2 (1,3)
__device__ __forceinline__ float mlp3(float f0,float f1,float f2,
                                      const float* W1,const float* b1,
                                      const float* W2,float b2){
    float h0=fmaxf(fmaf(W1[0],f0,fmaf(W1[1],f1,fmaf(W1[2],f2,b1[0]))),0.f);
    float h1=fmaxf(fmaf(W1[3],f0,fmaf(W1[4],f1,fmaf(W1[5],f2,b1[1]))),0.f);
    float h2=fmaxf(fmaf(W1[6],f0,fmaf(W1[7],f1,fmaf(W1[8],f2,b1[2]))),0.f);
    return fmaxf(fmaf(W2[0],h0,fmaf(W2[1],h1,fmaf(W2[2],h2,b2))),0.f);
}

__global__ void k_zero_rowsum(){
    int i = blockIdx.x*blockDim.x + threadIdx.x;
    if (i < B_*L_) g_rowsum[i] = 0.f;
}

// Init: uu = soft_sign(u-S)*u ; a_hat = sigmoid(uu)*soft_sign(uu-S)
// a0 = 0.5*(ah_ij^2 + ah_ji^2)*m ; rowsum0 accumulated (a0 not output)
__global__ __launch_bounds__(256) void k_init(const float* __restrict__ u,
                                              const float* __restrict__ x){
    int tj = blockIdx.x, ti = blockIdx.y, b = blockIdx.z;
    if (tj < ti) return;
    bool diag = (ti == tj);
    __shared__ float s_ahA[TILE][TILE+1];
    __shared__ float s_ahB[TILE][TILE+1];
    __shared__ float s_xI[TILE][4], s_xJ[TILE][4];
    __shared__ float s_rsI[TILE], s_rsJ[TILE];
    int tid = threadIdx.x, lane = tid & 31, w = tid >> 5;

    if (tid < TILE*4){ int r = tid>>2, k = tid&3;
        s_xI[r][k] = x[(b*L_ + ti*TILE + r)*4 + k];
        s_xJ[r][k] = x[(b*L_ + tj*TILE + r)*4 + k];
    }
    if (tid >= 128 && tid < 128+TILE){ s_rsI[tid-128]=0.f; s_rsJ[tid-128]=0.f; }

    size_t base = (size_t)b*L_*L_;
    #pragma unroll
    for (int k=0;k<4;k++){
        int r = k*8 + w;
        {
            size_t idx = base + (size_t)(ti*TILE+r)*L_ + tj*TILE + lane;
            float uv = u[idx];
            float uu = sigm(2.f*(uv - S_CONST))*uv;
            float ah = sigm(uu)*sigm(2.f*(uu - S_CONST));
            g_uu[idx]=uu; g_ah[idx]=ah; s_ahA[r][lane]=ah;
        }
        if (!diag){
            size_t idx = base + (size_t)(tj*TILE+r)*L_ + ti*TILE + lane;
            float uv = u[idx];
            float uu = sigm(2.f*(uv - S_CONST))*uv;
            float ah = sigm(uu)*sigm(2.f*(uu - S_CONST));
            g_uu[idx]=uu; g_ah[idx]=ah; s_ahB[r][lane]=ah;
        }
    }
    __syncthreads();
    #pragma unroll
    for (int k=0;k<4;k++){
        int r = k*8 + w;
        {
            float aij = s_ahA[r][lane];
            float aji = diag ? s_ahA[lane][r] : s_ahB[lane][r];
            float m = m_of(s_xI[r], s_xJ[lane]);
            float a = 0.5f*(aij*aij + aji*aji)*m;
            float s = a;
            #pragma unroll
            for (int o=16;o>0;o>>=1) s += __shfl_xor_sync(0xffffffffu, s, o);
            if (lane==0) s_rsI[r] += s;
        }
        if (!diag){
            float bij = s_ahB[r][lane];
            float bji = s_ahA[lane][r];
            float m = m_of(s_xJ[r], s_xI[lane]);
            float a = 0.5f*(bij*bij + bji*bji)*m;
            float s = a;
            #pragma unroll
            for (int o=16;o>0;o>>=1) s += __shfl_xor_sync(0xffffffffu, s, o);
            if (lane==0) s_rsJ[r] += s;
        }
    }
    __syncthreads();
    if (tid < TILE){
        atomicAdd(&g_rowsum[b*L_ + ti*TILE + tid], s_rsI[tid]);
        if (!diag) atomicAdd(&g_rowsum[b*L_ + tj*TILE + tid], s_rsJ[tid]);
    }
}

// lmbd0 = relu(rowsum-1) ; g = lmbd0*soft_sign(rowsum-1) ; zero rowsum
__global__ void k_lam0(){
    int i = blockIdx.x*blockDim.x + threadIdx.x;
    if (i < B_*L_){
        float rs = g_rowsum[i];
        float l = fmaxf(rs - 1.f, 0.f);      // W_PEN = 1
        g_lmbd[i] = l;
        g_g[i] = l * sigm(2.f*(rs - 1.f));
        g_rowsum[i] = 0.f;
    }
}

// Per-row lambda MLP update after step t (t < T-1)
__global__ void k_lam(const float* __restrict__ lW1,const float* __restrict__ lb1,
                      const float* __restrict__ lW2,const float* __restrict__ lb2,int t){
    int i = blockIdx.x*blockDim.x + threadIdx.x;
    if (i < B_*L_){
        float rs = g_rowsum[i];
        float lg = fmaxf(rs - 1.f, 0.f);
        float l0 = g_lmbd[i];
        const float* W1 = lW1 + t*6;
        const float* b1 = lb1 + t*3;
        const float* W2 = lW2 + t*3;
        float h0 = fmaxf(fmaf(W1[0],l0,fmaf(W1[1],lg,b1[0])),0.f);
        float h1 = fmaxf(fmaf(W1[2],l0,fmaf(W1[3],lg,b1[1])),0.f);
        float h2 = fmaxf(fmaf(W1[4],l0,fmaf(W1[5],lg,b1[2])),0.f);
        float ln = fmaxf(fmaf(W2[0],h0,fmaf(W2[1],h1,fmaf(W2[2],h2,__ldg(lb2+t)))),0.f);
        g_lmbd[i] = ln;
        g_g[i] = ln * sigm(2.f*(rs - 1.f));
        g_rowsum[i] = 0.f;
    }
}

// Main per-timestep kernel: one block owns tile pair (I,J)+(J,I).
// Updates a_hat in place, writes out a[t], accumulates rowsums.
__global__ __launch_bounds__(256) void k_step(int t, float* __restrict__ out,
    const float* __restrict__ x,
    const float* __restrict__ aW1,const float* __restrict__ ab1,
    const float* __restrict__ aW2,const float* __restrict__ ab2,
    const float* __restrict__ rW1,const float* __restrict__ rb1,
    const float* __restrict__ rW2,const float* __restrict__ rb2){
    int tj = blockIdx.x, ti = blockIdx.y, b = blockIdx.z;
    if (tj < ti) return;
    bool diag = (ti == tj);
    __shared__ float s_uuA[TILE][TILE+1], s_uuB[TILE][TILE+1];
    __shared__ float s_anA[TILE][TILE+1], s_anB[TILE][TILE+1];
    __shared__ float s_xI[TILE][4], s_xJ[TILE][4];
    __shared__ float s_gI[TILE], s_gJ[TILE];
    __shared__ float s_rsI[TILE], s_rsJ[TILE];
    __shared__ float sW[32]; // [0..8]=aW1 [9..11]=ab1 [12..14]=aW2 [15]=ab2
                             // [16..24]=rW1 [25..27]=rb1 [28..30]=rW2 [31]=rb2
    int tid = threadIdx.x, lane = tid & 31, w = tid >> 5;

    if (tid < 9){ sW[tid]    = __ldg(aW1 + t*9 + tid);
                  sW[16+tid] = __ldg(rW1 + t*9 + tid); }
    if (tid >= 32 && tid < 35){ int i=tid-32;
        sW[9+i]  = __ldg(ab1 + t*3 + i);
        sW[25+i] = __ldg(rb1 + t*3 + i); }
    if (tid >= 64 && tid < 67){ int i=tid-64;
        sW[12+i] = __ldg(aW2 + t*3 + i);
        sW[28+i] = __ldg(rW2 + t*3 + i); }
    if (tid == 96){ sW[15] = __ldg(ab2 + t); sW[31] = __ldg(rb2 + t); }

    if (tid < TILE*4){ int r = tid>>2, k = tid&3;
        s_xI[r][k] = x[(b*L_ + ti*TILE + r)*4 + k];
        s_xJ[r][k] = x[(b*L_ + tj*TILE + r)*4 + k];
    }
    if (tid >= 128 && tid < 128+TILE){ int r = tid-128;
        s_gI[r] = g_g[b*L_ + ti*TILE + r];
        s_gJ[r] = g_g[b*L_ + tj*TILE + r];
        s_rsI[r] = 0.f; s_rsJ[r] = 0.f;
    }
    size_t base = (size_t)b*L_*L_;
    #pragma unroll
    for (int k=0;k<4;k++){
        int r = k*8 + w;
        s_uuA[r][lane] = g_uu[base + (size_t)(ti*TILE+r)*L_ + tj*TILE + lane];
        if (!diag)
            s_uuB[r][lane] = g_uu[base + (size_t)(tj*TILE+r)*L_ + ti*TILE + lane];
    }
    __syncthreads();

    // Phase A: ah_new per element (needs uu transpose + row scalars only)
    #pragma unroll
    for (int k=0;k<4;k++){
        int r = k*8 + w;
        {
            float uij = s_uuA[r][lane];
            float uji = diag ? s_uuA[lane][r] : s_uuB[lane][r];
            float gf = fmaf(-0.5f, uij+uji, s_gI[r] + s_gJ[lane]);
            size_t idx = base + (size_t)(ti*TILE+r)*L_ + tj*TILE + lane;
            float ahv = __ldg(&g_ah[idx]);
            float m = m_of(s_xI[r], s_xJ[lane]);
            float grad = ahv*m*gf;
            float v   = mlp3(ahv,grad,uij,&sW[0], &sW[9], &sW[12], sW[15]);
            float rho = mlp3(ahv,grad,uij,&sW[16],&sW[25],&sW[28], sW[31]);
            float ahn = fminf(fmaxf(v - rho, 0.f), 1.f);
            s_anA[r][lane] = ahn;
            g_ah[idx] = ahn;
        }
        if (!diag){
            float uij = s_uuB[r][lane];
            float uji = s_uuA[lane][r];
            float gf = fmaf(-0.5f, uij+uji, s_gJ[r] + s_gI[lane]);
            size_t idx = base + (size_t)(tj*TILE+r)*L_ + ti*TILE + lane;
            float ahv = __ldg(&g_ah[idx]);
            float m = m_of(s_xJ[r], s_xI[lane]);
            float grad = ahv*m*gf;
            float v   = mlp3(ahv,grad,uij,&sW[0], &sW[9], &sW[12], sW[15]);
            float rho = mlp3(ahv,grad,uij,&sW[16],&sW[25],&sW[28], sW[31]);
            float ahn = fminf(fmaxf(v - rho, 0.f), 1.f);
            s_anB[r][lane] = ahn;
            g_ah[idx] = ahn;
        }
    }
    __syncthreads();

    // Phase B: a = contact(ah_new), coalesced writes both orientations + rowsums
    float* outT = out + (size_t)t*B_*L_*L_;
    #pragma unroll
    for (int k=0;k<4;k++){
        int r = k*8 + w;
        {
            float aij = s_anA[r][lane];
            float aji = diag ? s_anA[lane][r] : s_anB[lane][r];
            float m = m_of(s_xI[r], s_xJ[lane]);
            float a = 0.5f*(aij*aij + aji*aji)*m;
            outT[base + (size_t)(ti*TILE+r)*L_ + tj*TILE + lane] = a;
            float s = a;
            #pragma unroll
            for (int o=16;o>0;o>>=1) s += __shfl_xor_sync(0xffffffffu, s, o);
            if (lane==0) s_rsI[r] += s;
        }
        if (!diag){
            float aij = s_anB[r][lane];
            float aji = s_anA[lane][r];
            float m = m_of(s_xJ[r], s_xI[lane]);
            float a = 0.5f*(aij*aij + aji*aji)*m;
            outT[base + (size_t)(tj*TILE+r)*L_ + ti*TILE + lane] = a;
            float s = a;
            #pragma unroll
            for (int o=16;o>0;o>>=1) s += __shfl_xor_sync(0xffffffffu, s, o);
            if (lane==0) s_rsJ[r] += s;
        }
    }
    __syncthreads();
    if (tid < TILE){
        atomicAdd(&g_rowsum[b*L_ + ti*TILE + tid], s_rsI[tid]);
        if (!diag) atomicAdd(&g_rowsum[b*L_ + tj*TILE + tid], s_rsJ[tid]);
    }
}

extern "C" void kernel_launch(void* const* d_in, const int* in_sizes, int n_in,
                              void* d_out, int out_size){
    const float* u = (const float*)d_in[0];
    const float* x = (const float*)d_in[1];
    // 'timesteps' scalar may or may not occupy a slot; detect it.
    int wb = 2;
    if (n_in >= 15 && in_sizes[2] == 1) wb = 3;
    const float* aW1 = (const float*)d_in[wb+0];
    const float* ab1 = (const float*)d_in[wb+1];
    const float* aW2 = (const float*)d_in[wb+2];
    const float* ab2 = (const float*)d_in[wb+3];
    const float* rW1 = (const float*)d_in[wb+4];
    const float* rb1 = (const float*)d_in[wb+5];
    const float* rW2 = (const float*)d_in[wb+6];
    const float* rb2 = (const float*)d_in[wb+7];
    const float* lW1 = (const float*)d_in[wb+8];
    const float* lb1 = (const float*)d_in[wb+9];
    const float* lW2 = (const float*)d_in[wb+10];
    const float* lb2 = (const float*)d_in[wb+11];
    float* out = (float*)d_out;

    dim3 grid(NT, NT, B_);
    k_zero_rowsum<<<(B_*L_+255)/256, 256>>>();
    k_init<<<grid, 256>>>(u, x);
    k_lam0<<<(B_*L_+255)/256, 256>>>();
    for (int t=0; t<T_; t++){
        k_step<<<grid, 256>>>(t, out, x, aW1,ab1,aW2,ab2, rW1,rb1,rW2,rb2);
        if (t+1 < T_)
            k_lam<<<(B_*L_+255)/256, 256>>>(lW1, lb1, lW2, lb2, t);
    }
    (void)out_size;
}

// round 4
// speedup vs baseline: 1.4922x; 1.4922x over previous
#include <cuda_runtime.h>

#define B_ 8
#define L_ 1024
#define T_ 10
#define TILE 32
#define NTRI 528            // 32*33/2 upper-triangle tile pairs
#define SP 33               // padded shared stride (floats)
#define S_CONST 2.1972245773362196f   // log(9)

// Scratch (__device__ globals: allocation-free rule)
__device__ float g_uu[(size_t)B_*L_*L_];
__device__ float g_ah[(size_t)B_*L_*L_];
__device__ float g_rowsum[B_*L_];
__device__ float g_lmbd[B_*L_];
__device__ float g_g[B_*L_];

// MLP weights in constant memory (filled by D2D memcpy at launch/capture)
__constant__ float c_aW1[T_*9], c_ab1[T_*3], c_aW2[T_*3], c_ab2[T_];
__constant__ float c_rW1[T_*9], c_rb1[T_*3], c_rW2[T_*3], c_rb2[T_];

__device__ __forceinline__ float sigm(float x){ return 1.0f/(1.0f+__expf(-x)); }

// p = tj*(tj+1)/2 + ti  with ti <= tj
__device__ __forceinline__ void tri_decode(int p, int& ti, int& tj){
    int a = (int)((sqrtf(8.0f*(float)p + 1.0f) - 1.0f) * 0.5f);
    while ((a+1)*(a+2)/2 <= p) a++;
    while (a*(a+1)/2 > p) a--;
    tj = a; ti = p - a*(a+1)/2;
}

__device__ __forceinline__ float mlp3(float f0,float f1,float f2,
                                      const float* W1,const float* b1,
                                      const float* W2,float b2){
    float h0=fmaxf(fmaf(W1[0],f0,fmaf(W1[1],f1,fmaf(W1[2],f2,b1[0]))),0.f);
    float h1=fmaxf(fmaf(W1[3],f0,fmaf(W1[4],f1,fmaf(W1[5],f2,b1[1]))),0.f);
    float h2=fmaxf(fmaf(W1[6],f0,fmaf(W1[7],f1,fmaf(W1[8],f2,b1[2]))),0.f);
    return fmaxf(fmaf(W2[0],h0,fmaf(W2[1],h1,fmaf(W2[2],h2,b2))),0.f);
}

__device__ __forceinline__ float dot4(float4 a, float4 b){
    return fmaf(a.x,b.x, fmaf(a.y,b.y, fmaf(a.z,b.z, a.w*b.w)));
}

__global__ void k_zero_rowsum(){
    int i = blockIdx.x*blockDim.x + threadIdx.x;
    if (i < B_*L_) g_rowsum[i] = 0.f;
}

// ---------------------------------------------------------------------------
// Init: uu = soft_sign(u-S)*u ; ah = sigmoid(uu)*soft_sign(uu-S);
// rowsum0 = sum_j contact(ah)
// ---------------------------------------------------------------------------
__global__ __launch_bounds__(256) void k_init(const float4* __restrict__ u4,
                                              const float4* __restrict__ x4){
    int b = blockIdx.y;
    int ti, tj; tri_decode(blockIdx.x, ti, tj);
    bool diag = (ti == tj);
    __shared__ float s_ahA[TILE*SP], s_ahB[TILE*SP];
    __shared__ float4 s_cI[TILE], s_cJ[TILE];   // combos for ti-tile / tj-tile rows

    int tid = threadIdx.x;
    int r  = tid >> 3;            // row within tile
    int c0 = (tid & 7) * 4;       // column base

    if (tid < 64){
        int q = tid & 31;
        int rowg = ((tid < 32) ? tj : ti)*TILE + q;
        float4 xr = x4[b*L_ + rowg];
        float4 c = make_float4(xr.y, xr.x + xr.w, xr.w, xr.y + xr.z);
        if (tid < 32) s_cJ[q] = c; else s_cI[q] = c;
    }

    const int L4 = L_/4;
    size_t idxA4 = (size_t)b*L_*L4 + (size_t)(ti*TILE + r)*L4 + tj*8 + (tid & 7);
    size_t idxB4 = (size_t)b*L_*L4 + (size_t)(tj*TILE + r)*L4 + ti*8 + (tid & 7);

    float4* uu4 = reinterpret_cast<float4*>(g_uu);
    float4* ah4 = reinterpret_cast<float4*>(g_ah);

    float ahAa[4], ahBa[4];
    {
        float4 uv = u4[idxA4];
        float ua[4] = {uv.x, uv.y, uv.z, uv.w};
        float uua[4];
        #pragma unroll
        for (int s=0;s<4;s++){
            float uu = sigm(2.f*(ua[s]-S_CONST))*ua[s];
            uua[s] = uu;
            float ah = sigm(uu)*sigm(2.f*(uu-S_CONST));
            ahAa[s] = ah;
            s_ahA[r*SP + c0 + s] = ah;
        }
        uu4[idxA4] = make_float4(uua[0],uua[1],uua[2],uua[3]);
        ah4[idxA4] = make_float4(ahAa[0],ahAa[1],ahAa[2],ahAa[3]);
    }
    if (!diag){
        float4 uv = u4[idxB4];
        float ua[4] = {uv.x, uv.y, uv.z, uv.w};
        float uua[4];
        #pragma unroll
        for (int s=0;s<4;s++){
            float uu = sigm(2.f*(ua[s]-S_CONST))*ua[s];
            uua[s] = uu;
            float ah = sigm(uu)*sigm(2.f*(uu-S_CONST));
            ahBa[s] = ah;
            s_ahB[r*SP + c0 + s] = ah;
        }
        uu4[idxB4] = make_float4(uua[0],uua[1],uua[2],uua[3]);
        ah4[idxB4] = make_float4(ahBa[0],ahBa[1],ahBa[2],ahBa[3]);
    }
    float4 xiA = x4[b*L_ + ti*TILE + r];
    float4 xiB = x4[b*L_ + tj*TILE + r];
    __syncthreads();

    float sumA = 0.f, sumB = 0.f;
    #pragma unroll
    for (int s=0;s<4;s++){
        float m = dot4(xiA, s_cJ[c0+s]);
        float aji = (diag ? s_ahA : s_ahB)[(c0+s)*SP + r];
        sumA += 0.5f*(ahAa[s]*ahAa[s] + aji*aji)*m;
    }
    if (!diag){
        #pragma unroll
        for (int s=0;s<4;s++){
            float m = dot4(xiB, s_cI[c0+s]);
            float aji = s_ahA[(c0+s)*SP + r];
            sumB += 0.5f*(ahBa[s]*ahBa[s] + aji*aji)*m;
        }
    }
    #pragma unroll
    for (int o=1;o<8;o<<=1){
        sumA += __shfl_xor_sync(0xffffffffu, sumA, o);
        sumB += __shfl_xor_sync(0xffffffffu, sumB, o);
    }
    if ((tid & 7) == 0){
        atomicAdd(&g_rowsum[b*L_ + ti*TILE + r], sumA);
        if (!diag) atomicAdd(&g_rowsum[b*L_ + tj*TILE + r], sumB);
    }
}

__global__ void k_lam0(){
    int i = blockIdx.x*blockDim.x + threadIdx.x;
    if (i < B_*L_){
        float rs = g_rowsum[i];
        float l = fmaxf(rs - 1.f, 0.f);           // W_PEN = 1
        g_lmbd[i] = l;
        g_g[i] = l * sigm(2.f*(rs - 1.f));
        g_rowsum[i] = 0.f;
    }
}

__global__ void k_lam(const float* __restrict__ lW1,const float* __restrict__ lb1,
                      const float* __restrict__ lW2,const float* __restrict__ lb2,int t){
    int i = blockIdx.x*blockDim.x + threadIdx.x;
    if (i < B_*L_){
        float rs = g_rowsum[i];
        float lg = fmaxf(rs - 1.f, 0.f);
        float l0 = g_lmbd[i];
        const float* W1 = lW1 + t*6;
        const float* b1 = lb1 + t*3;
        const float* W2 = lW2 + t*3;
        float h0 = fmaxf(fmaf(W1[0],l0,fmaf(W1[1],lg,b1[0])),0.f);
        float h1 = fmaxf(fmaf(W1[2],l0,fmaf(W1[3],lg,b1[1])),0.f);
        float h2 = fmaxf(fmaf(W1[4],l0,fmaf(W1[5],lg,b1[2])),0.f);
        float ln = fmaxf(fmaf(W2[0],h0,fmaf(W2[1],h1,fmaf(W2[2],h2,__ldg(lb2+t)))),0.f);
        g_lmbd[i] = ln;
        g_g[i] = ln * sigm(2.f*(rs - 1.f));
        g_rowsum[i] = 0.f;
    }
}

// ---------------------------------------------------------------------------
// Per-timestep fused step: block owns tile pair (I,J)+(J,I).
// ---------------------------------------------------------------------------
__global__ __launch_bounds__(256) void k_step(int t, int last, float* __restrict__ out,
                                              const float4* __restrict__ x4){
    int b = blockIdx.y;
    int ti, tj; tri_decode(blockIdx.x, ti, tj);
    bool diag = (ti == tj);
    __shared__ float s_uuA[TILE*SP], s_uuB[TILE*SP];
    __shared__ float s_anA[TILE*SP], s_anB[TILE*SP];
    __shared__ float4 s_cI[TILE], s_cJ[TILE];
    __shared__ float s_gI[TILE], s_gJ[TILE];

    int tid = threadIdx.x;
    int r  = tid >> 3;
    int c0 = (tid & 7) * 4;

    if (tid < 64){
        int q = tid & 31;
        int rowg = ((tid < 32) ? tj : ti)*TILE + q;
        float4 xr = x4[b*L_ + rowg];
        float4 c = make_float4(xr.y, xr.x + xr.w, xr.w, xr.y + xr.z);
        float gv = g_g[b*L_ + rowg];
        if (tid < 32){ s_cJ[q] = c; s_gJ[q] = gv; }
        else         { s_cI[q] = c; s_gI[q] = gv; }
    }

    const int L4 = L_/4;
    size_t idxA4 = (size_t)b*L_*L4 + (size_t)(ti*TILE + r)*L4 + tj*8 + (tid & 7);
    size_t idxB4 = (size_t)b*L_*L4 + (size_t)(tj*TILE + r)*L4 + ti*8 + (tid & 7);

    const float4* uu4 = reinterpret_cast<const float4*>(g_uu);
    const float4* ah4 = reinterpret_cast<const float4*>(g_ah);
    float4* ahw4 = reinterpret_cast<float4*>(g_ah);

    float4 uuAv = uu4[idxA4];
    float4 ahAv = ah4[idxA4];
    float uuAa[4] = {uuAv.x, uuAv.y, uuAv.z, uuAv.w};
    float ahAa[4] = {ahAv.x, ahAv.y, ahAv.z, ahAv.w};
    #pragma unroll
    for (int s=0;s<4;s++) s_uuA[r*SP + c0 + s] = uuAa[s];

    float uuBa[4], ahBa[4];
    if (!diag){
        float4 uuBv = uu4[idxB4];
        float4 ahBv = ah4[idxB4];
        uuBa[0]=uuBv.x; uuBa[1]=uuBv.y; uuBa[2]=uuBv.z; uuBa[3]=uuBv.w;
        ahBa[0]=ahBv.x; ahBa[1]=ahBv.y; ahBa[2]=ahBv.z; ahBa[3]=ahBv.w;
        #pragma unroll
        for (int s=0;s<4;s++) s_uuB[r*SP + c0 + s] = uuBa[s];
    }
    float4 xiA = x4[b*L_ + ti*TILE + r];
    float4 xiB = x4[b*L_ + tj*TILE + r];
    __syncthreads();

    // m held in registers for both phases
    float mA[4], mB[4];
    #pragma unroll
    for (int s=0;s<4;s++){
        mA[s] = dot4(xiA, s_cJ[c0+s]);
        mB[s] = dot4(xiB, s_cI[c0+s]);
    }
    float gIr = s_gI[r];
    float gJr = s_gJ[r];

    const float* aW1 = &c_aW1[t*9]; const float* ab1 = &c_ab1[t*3];
    const float* aW2 = &c_aW2[t*3]; float ab2 = c_ab2[t];
    const float* rW1 = &c_rW1[t*9]; const float* rb1 = &c_rb1[t*3];
    const float* rW2 = &c_rW2[t*3]; float rb2 = c_rb2[t];

    // Phase A: new a_hat
    float anA[4], anB[4];
    #pragma unroll
    for (int s=0;s<4;s++){
        float uij = uuAa[s];
        float uji = (diag ? s_uuA : s_uuB)[(c0+s)*SP + r];
        float gf  = fmaf(-0.5f, uij + uji, gIr + s_gJ[c0+s]);
        float ahv = ahAa[s];
        float grad = ahv * mA[s] * gf;
        float v   = mlp3(ahv, grad, uij, aW1, ab1, aW2, ab2);
        float rho = mlp3(ahv, grad, uij, rW1, rb1, rW2, rb2);
        float ahn = fminf(fmaxf(v - rho, 0.f), 1.f);
        anA[s] = ahn;
        s_anA[r*SP + c0 + s] = ahn;
    }
    ahw4[idxA4] = make_float4(anA[0], anA[1], anA[2], anA[3]);
    if (!diag){
        #pragma unroll
        for (int s=0;s<4;s++){
            float uij = uuBa[s];
            float uji = s_uuA[(c0+s)*SP + r];
            float gf  = fmaf(-0.5f, uij + uji, gJr + s_gI[c0+s]);
            float ahv = ahBa[s];
            float grad = ahv * mB[s] * gf;
            float v   = mlp3(ahv, grad, uij, aW1, ab1, aW2, ab2);
            float rho = mlp3(ahv, grad, uij, rW1, rb1, rW2, rb2);
            float ahn = fminf(fmaxf(v - rho, 0.f), 1.f);
            anB[s] = ahn;
            s_anB[r*SP + c0 + s] = ahn;
        }
        ahw4[idxB4] = make_float4(anB[0], anB[1], anB[2], anB[3]);
    }
    __syncthreads();

    // Phase B: a = contact(ah_new) -> out, rowsums
    float4* out4 = reinterpret_cast<float4*>(out + (size_t)t*B_*L_*L_);
    float sumA = 0.f, sumB = 0.f;
    {
        float av[4];
        #pragma unroll
        for (int s=0;s<4;s++){
            float aji = (diag ? s_anA : s_anB)[(c0+s)*SP + r];
            float a = 0.5f*(anA[s]*anA[s] + aji*aji)*mA[s];
            av[s] = a; sumA += a;
        }
        __stcs(&out4[idxA4], make_float4(av[0],av[1],av[2],av[3]));
    }
    if (!diag){
        float av[4];
        #pragma unroll
        for (int s=0;s<4;s++){
            float aji = s_anA[(c0+s)*SP + r];
            float a = 0.5f*(anB[s]*anB[s] + aji*aji)*mB[s];
            av[s] = a; sumB += a;
        }
        __stcs(&out4[idxB4], make_float4(av[0],av[1],av[2],av[3]));
    }
    if (!last){
        #pragma unroll
        for (int o=1;o<8;o<<=1){
            sumA += __shfl_xor_sync(0xffffffffu, sumA, o);
            sumB += __shfl_xor_sync(0xffffffffu, sumB, o);
        }
        if ((tid & 7) == 0){
            atomicAdd(&g_rowsum[b*L_ + ti*TILE + r], sumA);
            if (!diag) atomicAdd(&g_rowsum[b*L_ + tj*TILE + r], sumB);
        }
    }
}

extern "C" void kernel_launch(void* const* d_in, const int* in_sizes, int n_in,
                              void* d_out, int out_size){
    const float* u = (const float*)d_in[0];
    const float* x = (const float*)d_in[1];
    int wb = 2;
    if (n_in >= 15 && in_sizes[2] == 1) wb = 3;
    const float* aW1 = (const float*)d_in[wb+0];
    const float* ab1 = (const float*)d_in[wb+1];
    const float* aW2 = (const float*)d_in[wb+2];
    const float* ab2 = (const float*)d_in[wb+3];
    const float* rW1 = (const float*)d_in[wb+4];
    const float* rb1 = (const float*)d_in[wb+5];
    const float* rW2 = (const float*)d_in[wb+6];
    const float* rb2 = (const float*)d_in[wb+7];
    const float* lW1 = (const float*)d_in[wb+8];
    const float* lb1 = (const float*)d_in[wb+9];
    const float* lW2 = (const float*)d_in[wb+10];
    const float* lb2 = (const float*)d_in[wb+11];
    float* out = (float*)d_out;

    // Weights -> constant memory (D2D memcpy nodes; graph-capturable)
    cudaMemcpyToSymbolAsync(c_aW1, aW1, T_*9*sizeof(float), 0, cudaMemcpyDeviceToDevice, 0);
    cudaMemcpyToSymbolAsync(c_ab1, ab1, T_*3*sizeof(float), 0, cudaMemcpyDeviceToDevice, 0);
    cudaMemcpyToSymbolAsync(c_aW2, aW2, T_*3*sizeof(float), 0, cudaMemcpyDeviceToDevice, 0);
    cudaMemcpyToSymbolAsync(c_ab2, ab2, T_*1*sizeof(float), 0, cudaMemcpyDeviceToDevice, 0);
    cudaMemcpyToSymbolAsync(c_rW1, rW1, T_*9*sizeof(float), 0, cudaMemcpyDeviceToDevice, 0);
    cudaMemcpyToSymbolAsync(c_rb1, rb1, T_*3*sizeof(float), 0, cudaMemcpyDeviceToDevice, 0);
    cudaMemcpyToSymbolAsync(c_rW2, rW2, T_*3*sizeof(float), 0, cudaMemcpyDeviceToDevice, 0);
    cudaMemcpyToSymbolAsync(c_rb2, rb2, T_*1*sizeof(float), 0, cudaMemcpyDeviceToDevice, 0);

    dim3 grid(NTRI, B_);
    k_zero_rowsum<<<(B_*L_+255)/256, 256>>>();
    k_init<<<grid, 256>>>((const float4*)u, (const float4*)x);
    k_lam0<<<(B_*L_+255)/256, 256>>>();
    for (int t=0; t<T_; t++){
        k_step<<<grid, 256>>>(t, (t==T_-1) ? 1 : 0, out, (const float4*)x);
        if (t+1 < T_)
            k_lam<<<(B_*L_+255)/256, 256>>>(lW1, lb1, lW2, lb2, t);
    }
    (void)out_size;
}